// round 10
// baseline (speedup 1.0000x reference)
#include <cuda_runtime.h>
#include <math.h>

#define S_LEN   2048
#define D_MODEL 1024
#define NH      16
#define HD      64
#define BATCH   4
#define M_TOTAL (BATCH * S_LEN)          // 8192
#define PLANE   (8192 * 1024)            // elems per Q/K/V plane

// Scratch (__device__ globals = sanctioned scratch, allocation-free rule):
//  g_qkv : Q,K,V in [b,h,s,d], values pre-rounded to tf32 (Q pre-scaled 0.125)
//  g_x32 : hidden_states pre-rounded to tf32 bits
//  g_w32 : Wq|Wk|Wv pre-rounded to tf32 bits
__device__ float    g_qkv[3ull * PLANE];
__device__ unsigned g_x32[(size_t)M_TOTAL * D_MODEL];
__device__ unsigned g_w32[3ull * D_MODEL * D_MODEL];

// ---------------------------------------------------------------------------
// tf32 mma helpers (m16n8k8, row.col, f32 accumulate)
//   A: a0=[grp][lk] a1=[grp+8][lk] a2=[grp][lk+4] a3=[grp+8][lk+4]
//   B (row-major [n][k]): b0=[n+grp][lk] b1=[n+grp][lk+4]
//   C: c0=[grp][2lk] c1=[grp][2lk+1] c2=[grp+8][2lk] c3=[grp+8][2lk+1]
// ---------------------------------------------------------------------------
__device__ __forceinline__ unsigned f2tf(float f) {
    unsigned u;
    asm("cvt.rna.tf32.f32 %0, %1;" : "=r"(u) : "f"(f));
    return u;
}

__device__ __forceinline__ void mma_tf32(float c[4], const unsigned a[4],
                                         const unsigned b[2]) {
    asm volatile(
        "mma.sync.aligned.m16n8k8.row.col.f32.tf32.tf32.f32 "
        "{%0,%1,%2,%3}, {%4,%5,%6,%7}, {%8,%9}, {%0,%1,%2,%3};"
        : "+f"(c[0]), "+f"(c[1]), "+f"(c[2]), "+f"(c[3])
        : "r"(a[0]), "r"(a[1]), "r"(a[2]), "r"(a[3]), "r"(b[0]), "r"(b[1]));
}

__device__ __forceinline__ void cp_async16(void* sp, const void* gp) {
    unsigned saddr = (unsigned)__cvta_generic_to_shared(sp);
    asm volatile("cp.async.cg.shared.global [%0], [%1], 16;\n"
                 :: "r"(saddr), "l"(gp));
}
#define CP_COMMIT() asm volatile("cp.async.commit_group;")
#define CP_WAIT(N)  asm volatile("cp.async.wait_group %0;" :: "n"(N))

// ---------------------------------------------------------------------------
// Kernel 0: pre-round X and W to tf32 bits (memory-bound, ~14us measured).
// ---------------------------------------------------------------------------
__global__ __launch_bounds__(256) void cvt_prepass(
    const float* __restrict__ X,
    const float* __restrict__ Wq, const float* __restrict__ Wk,
    const float* __restrict__ Wv)
{
    const size_t X4 = (size_t)M_TOTAL * D_MODEL / 4;
    const size_t W4 = (size_t)D_MODEL * D_MODEL / 4;
    size_t i = (size_t)blockIdx.x * blockDim.x + threadIdx.x;
    if (i >= X4 + 3 * W4) return;

    const float* src;
    unsigned*    dst;
    if (i < X4)                { src = X;  dst = g_x32;              }
    else if (i < X4 + W4)      { src = Wq; dst = g_w32;              i -= X4; }
    else if (i < X4 + 2 * W4)  { src = Wk; dst = g_w32 +     W4 * 4; i -= X4 + W4; }
    else                       { src = Wv; dst = g_w32 + 2 * W4 * 4; i -= X4 + 2 * W4; }

    float4 v = *(const float4*)(src + i * 4);
    uint4  u = { f2tf(v.x), f2tf(v.y), f2tf(v.z), f2tf(v.w) };
    *(uint4*)(dst + i * 4) = u;
}

// ---------------------------------------------------------------------------
// Kernel 1: fused QKV projection, tf32, cp.async double-buffered.
//   Inputs pre-rounded tf32 bits -> zero cvt in the mainloop.
// ---------------------------------------------------------------------------
#define GBM 128
#define GBN 128
#define GBK 32
#define GPAD (GBK + 4)               // 36 words
#define GTILE (GBM * GPAD)

__global__ __launch_bounds__(256, 2) void qkv_gemm_tf32(
    const float* __restrict__ bq, const float* __restrict__ bk,
    const float* __restrict__ bv)
{
    extern __shared__ unsigned psm[];   // As[2][128][36] | Bs[2][128][36]

    const int z = blockIdx.z;
    const unsigned* X    = g_x32;
    const unsigned* W    = g_w32 + (size_t)z * D_MODEL * D_MODEL;
    const float*    bias = (z == 0) ? bq : (z == 1) ? bk : bv;
    const float     scale = (z == 0) ? 0.125f : 1.0f;
    float* Out = g_qkv + (size_t)z * PLANE;

    const int tid    = threadIdx.x;
    const int warp   = tid >> 5;
    const int lane   = tid & 31;
    const int grp    = lane >> 2;
    const int lk     = lane & 3;
    const int warp_m = warp >> 2;
    const int warp_n = warp & 3;
    const int m0 = blockIdx.y * GBM;
    const int n0 = blockIdx.x * GBN;

    const int sr  = tid >> 3;
    const int sc4 = tid & 7;

    float acc[4][4][4];
    #pragma unroll
    for (int mi = 0; mi < 4; mi++)
        #pragma unroll
        for (int ni = 0; ni < 4; ni++)
            #pragma unroll
            for (int r = 0; r < 4; r++) acc[mi][ni][r] = 0.f;

    #pragma unroll
    for (int it = 0; it < 4; it++) {
        int r = sr + it * 32;
        cp_async16(&psm[r * GPAD + sc4 * 4],
                   X + (size_t)(m0 + r) * D_MODEL + sc4 * 4);
        cp_async16(&psm[2 * GTILE + r * GPAD + sc4 * 4],
                   W + (size_t)(n0 + r) * D_MODEL + sc4 * 4);
    }
    CP_COMMIT();

    int p = 0;
    for (int k0 = 0; k0 < D_MODEL; k0 += GBK) {
        if (k0 + GBK < D_MODEL) {
            int q = p ^ 1;
            #pragma unroll
            for (int it = 0; it < 4; it++) {
                int r = sr + it * 32;
                cp_async16(&psm[q * GTILE + r * GPAD + sc4 * 4],
                           X + (size_t)(m0 + r) * D_MODEL + k0 + GBK + sc4 * 4);
                cp_async16(&psm[(2 + q) * GTILE + r * GPAD + sc4 * 4],
                           W + (size_t)(n0 + r) * D_MODEL + k0 + GBK + sc4 * 4);
            }
            CP_COMMIT();
            CP_WAIT(1);
        } else {
            CP_WAIT(0);
        }
        __syncthreads();

        const unsigned* Asb = psm + p * GTILE;
        const unsigned* Bsb = psm + (2 + p) * GTILE;

        #pragma unroll
        for (int kk = 0; kk < GBK; kk += 8) {
            unsigned a[4][4];
            #pragma unroll
            for (int mi = 0; mi < 4; mi++) {
                int rb = warp_m * 64 + mi * 16 + grp;
                a[mi][0] = Asb[(rb    ) * GPAD + kk + lk    ];
                a[mi][1] = Asb[(rb + 8) * GPAD + kk + lk    ];
                a[mi][2] = Asb[(rb    ) * GPAD + kk + lk + 4];
                a[mi][3] = Asb[(rb + 8) * GPAD + kk + lk + 4];
            }
            unsigned b[4][2];
            #pragma unroll
            for (int ni = 0; ni < 4; ni++) {
                int nb = warp_n * 32 + ni * 8 + grp;
                b[ni][0] = Bsb[nb * GPAD + kk + lk    ];
                b[ni][1] = Bsb[nb * GPAD + kk + lk + 4];
            }
            #pragma unroll
            for (int mi = 0; mi < 4; mi++)
                #pragma unroll
                for (int ni = 0; ni < 4; ni++)
                    mma_tf32(acc[mi][ni], a[mi], b[ni]);
        }
        __syncthreads();
        p ^= 1;
    }

    // epilogue: bias, pre-scale, round to tf32, scatter into [b, h, s, d]
    #pragma unroll
    for (int mi = 0; mi < 4; mi++) {
        #pragma unroll
        for (int half = 0; half < 2; half++) {
            int m  = m0 + warp_m * 64 + mi * 16 + grp + half * 8;
            int b_ = m >> 11;
            int s_ = m & 2047;
            #pragma unroll
            for (int ni = 0; ni < 4; ni++) {
                int n = n0 + warp_n * 32 + ni * 8 + 2 * lk;
                int h = n >> 6;
                int d = n & 63;
                float2 v;
                v.x = __uint_as_float(f2tf((acc[mi][ni][half * 2 + 0] + bias[n    ]) * scale));
                v.y = __uint_as_float(f2tf((acc[mi][ni][half * 2 + 1] + bias[n + 1]) * scale));
                *(float2*)&Out[(((size_t)(b_ * NH + h) * S_LEN + s_) << 6) + d] = v;
            }
        }
    }
}

// ---------------------------------------------------------------------------
// Kernel 2: causal flash attention, tf32 tensor cores.
// QT=128, 256 threads (8 warps x 16 rows). Q fragments in registers.
// Double-buffered K/V cp.async pipeline (regs cap CTAs at 2/SM, so the
// 71.7KB smem is free: 16 warps/SM either way). Each 64-key tile is
// amortized over 128 queries (half the staging of the QT=64 version).
// K: [key][68] (banks 4*grp+lk), V: [key][72] (banks 8*lk+grp): conflict-free.
// ---------------------------------------------------------------------------
#define QT   128
#define KT   64
#define KPAD 68
#define VPAD 72
#define KVTILE (KT * KPAD + KT * VPAD)   // words per stage: 8960

__global__ __launch_bounds__(256, 2) void attn_tc(
    const int* __restrict__ amask, float* __restrict__ out)
{
    extern __shared__ unsigned sm[];     // [2][ K 64x68 | V 64x72 ]
    float (*Ksb[2])[KPAD];
    float (*Vsb[2])[VPAD];
    Ksb[0] = (float(*)[KPAD])(sm);
    Vsb[0] = (float(*)[VPAD])(sm + KT * KPAD);
    Ksb[1] = (float(*)[KPAD])(sm + KVTILE);
    Vsb[1] = (float(*)[VPAD])(sm + KVTILE + KT * KPAD);

    const int qt = (gridDim.x - 1) - blockIdx.x;    // heavy blocks first
    const int bh = blockIdx.y;
    const int b_ = bh >> 4;
    const int h  = bh & 15;
    const int q0 = qt * QT;

    const float* Qb = g_qkv + (size_t)bh * S_LEN * HD;
    const float* Kb = g_qkv + (size_t)PLANE + (size_t)bh * S_LEN * HD;
    const float* Vb = g_qkv + 2ull * PLANE + (size_t)bh * S_LEN * HD;

    const int tid  = threadIdx.x;
    const int warp = tid >> 5;
    const int lane = tid & 31;
    const int grp  = lane >> 2;
    const int lk   = lane & 3;
    const int q0w  = q0 + warp * 16;    // this warp's first query row

    // ---- stage Q bits through buffer 0 region, hoist frags to registers ----
    // Q tile: 128 x 68 words = 34816 B <= KVTILE bytes (35840) ✓
    {
        unsigned (*Qstage)[KPAD] = (unsigned(*)[KPAD])(sm);
        #pragma unroll
        for (int it = 0; it < 8; it++) {
            int idx = tid + it * 256;      // 0..2047
            int r   = idx >> 4;            // q row 0..127
            int c   = idx & 15;            // 16B chunk
            uint4 u = *(const uint4*)(Qb + (size_t)(q0 + r) * HD + c * 4);
            *(uint4*)&Qstage[r][c * 4] = u;
        }
        __syncthreads();
    }
    unsigned aq[8][4];
    {
        unsigned (*Qstage)[KPAD] = (unsigned(*)[KPAD])(sm);
        const int rb = warp * 16;
        #pragma unroll
        for (int kk = 0; kk < 8; kk++) {
            aq[kk][0] = Qstage[rb + grp    ][kk * 8 + lk    ];
            aq[kk][1] = Qstage[rb + grp + 8][kk * 8 + lk    ];
            aq[kk][2] = Qstage[rb + grp    ][kk * 8 + lk + 4];
            aq[kk][3] = Qstage[rb + grp + 8][kk * 8 + lk + 4];
        }
        __syncthreads();   // Q reads done before buffer 0 is refilled
    }

    // staging coords: 64x64 tile = 1024 16B-chunks, 256 threads -> 4 iters
    const int kr = tid >> 4;               // 0..15
    const int kc = tid & 15;

    // ---- prologue: tile 0 into buffer 0 ----
    #pragma unroll
    for (int it = 0; it < 4; it++) {
        int r = kr + it * 16;
        cp_async16(&Ksb[0][r][kc * 4], Kb + (size_t)r * HD + kc * 4);
        cp_async16(&Vsb[0][r][kc * 4], Vb + (size_t)r * HD + kc * 4);
    }
    CP_COMMIT();

    float m_run[2] = { -1e30f, -1e30f };
    float l_run[2] = { 0.f, 0.f };
    float acc[8][4];
    #pragma unroll
    for (int ni = 0; ni < 8; ni++)
        #pragma unroll
        for (int r = 0; r < 4; r++) acc[ni][r] = 0.f;

    const int qsrc = lane & ~3;
    const int s1   = qsrc | (lk >> 1);
    const int s2   = s1 + 2;
    const int jmax = q0 + QT - KT;         // last tile start
    int p = 0;

    for (int j0 = 0; j0 <= jmax; j0 += KT) {
        // ---- issue next tile's loads, then wait for current tile ----
        if (j0 + KT <= jmax) {
            int q = p ^ 1;
            #pragma unroll
            for (int it = 0; it < 4; it++) {
                int r = kr + it * 16;
                cp_async16(&Ksb[q][r][kc * 4], Kb + (size_t)(j0 + KT + r) * HD + kc * 4);
                cp_async16(&Vsb[q][r][kc * 4], Vb + (size_t)(j0 + KT + r) * HD + kc * 4);
            }
            CP_COMMIT();
            CP_WAIT(1);
        } else {
            CP_WAIT(0);
        }
        __syncthreads();

        // warp-uniform skip: tile entirely above this warp's rows
        if (j0 <= q0w + 15) {
            float (*Kp)[KPAD] = Ksb[p];
            float (*Vp)[VPAD] = Vsb[p];

            // prefetch keep-mask (overlaps with mma)
            int2 km[8];
            #pragma unroll
            for (int ni = 0; ni < 8; ni++)
                km[ni] = *(const int2*)(amask + b_ * S_LEN + j0 + ni * 8 + 2 * lk);

            // ---- S = Q K^T ----
            float s[8][4];
            #pragma unroll
            for (int ni = 0; ni < 8; ni++)
                #pragma unroll
                for (int r = 0; r < 4; r++) s[ni][r] = 0.f;

            #pragma unroll
            for (int kk = 0; kk < 8; kk++) {
                #pragma unroll
                for (int ni = 0; ni < 8; ni++) {
                    unsigned b[2];
                    b[0] = __float_as_uint(Kp[ni * 8 + grp][kk * 8 + lk    ]);
                    b[1] = __float_as_uint(Kp[ni * 8 + grp][kk * 8 + lk + 4]);
                    mma_tf32(s[ni], aq[kk], b);
                }
            }

            // ---- causal mask (tiles touching the diagonal) ----
            if (j0 + KT - 1 > q0w) {
                int r0 = q0w + grp;
                #pragma unroll
                for (int ni = 0; ni < 8; ni++) {
                    int c0 = j0 + ni * 8 + 2 * lk;
                    if (c0     > r0    ) s[ni][0] = -1e30f;
                    if (c0 + 1 > r0    ) s[ni][1] = -1e30f;
                    if (c0     > r0 + 8) s[ni][2] = -1e30f;
                    if (c0 + 1 > r0 + 8) s[ni][3] = -1e30f;
                }
            }
            // ---- attention keep-mask ----
            #pragma unroll
            for (int ni = 0; ni < 8; ni++) {
                if (km[ni].x == 0) { s[ni][0] = -1e30f; s[ni][2] = -1e30f; }
                if (km[ni].y == 0) { s[ni][1] = -1e30f; s[ni][3] = -1e30f; }
            }

            // ---- online softmax ----
            float mt0 = -1e30f, mt1 = -1e30f;
            #pragma unroll
            for (int ni = 0; ni < 8; ni++) {
                mt0 = fmaxf(mt0, fmaxf(s[ni][0], s[ni][1]));
                mt1 = fmaxf(mt1, fmaxf(s[ni][2], s[ni][3]));
            }
            mt0 = fmaxf(mt0, __shfl_xor_sync(0xffffffffu, mt0, 1, 4));
            mt0 = fmaxf(mt0, __shfl_xor_sync(0xffffffffu, mt0, 2, 4));
            mt1 = fmaxf(mt1, __shfl_xor_sync(0xffffffffu, mt1, 1, 4));
            mt1 = fmaxf(mt1, __shfl_xor_sync(0xffffffffu, mt1, 2, 4));

            float mn0 = fmaxf(m_run[0], mt0);
            float mn1 = fmaxf(m_run[1], mt1);
            float al0 = __expf(m_run[0] - mn0);
            float al1 = __expf(m_run[1] - mn1);
            m_run[0] = mn0; m_run[1] = mn1;

            float lt0 = 0.f, lt1 = 0.f;
            #pragma unroll
            for (int ni = 0; ni < 8; ni++) {
                s[ni][0] = __expf(s[ni][0] - mn0); lt0 += s[ni][0];
                s[ni][1] = __expf(s[ni][1] - mn0); lt0 += s[ni][1];
                s[ni][2] = __expf(s[ni][2] - mn1); lt1 += s[ni][2];
                s[ni][3] = __expf(s[ni][3] - mn1); lt1 += s[ni][3];
            }
            lt0 += __shfl_xor_sync(0xffffffffu, lt0, 1, 4);
            lt0 += __shfl_xor_sync(0xffffffffu, lt0, 2, 4);
            lt1 += __shfl_xor_sync(0xffffffffu, lt1, 1, 4);
            lt1 += __shfl_xor_sync(0xffffffffu, lt1, 2, 4);
            l_run[0] = l_run[0] * al0 + lt0;
            l_run[1] = l_run[1] * al1 + lt1;

            #pragma unroll
            for (int ni = 0; ni < 8; ni++) {
                acc[ni][0] *= al0; acc[ni][1] *= al0;
                acc[ni][2] *= al1; acc[ni][3] *= al1;
            }

            // ---- P (C-frag) -> A-frag via quad shuffles, acc += P V ----
            #pragma unroll
            for (int kk = 0; kk < 8; kk++) {
                unsigned p0 = f2tf(s[kk][0]), p1 = f2tf(s[kk][1]);
                unsigned p2 = f2tf(s[kk][2]), p3 = f2tf(s[kk][3]);
                unsigned ap[4], t0, t1;
                t0 = __shfl_sync(0xffffffffu, p0, s1);
                t1 = __shfl_sync(0xffffffffu, p1, s1);
                ap[0] = (lk & 1) ? t1 : t0;
                t0 = __shfl_sync(0xffffffffu, p2, s1);
                t1 = __shfl_sync(0xffffffffu, p3, s1);
                ap[1] = (lk & 1) ? t1 : t0;
                t0 = __shfl_sync(0xffffffffu, p0, s2);
                t1 = __shfl_sync(0xffffffffu, p1, s2);
                ap[2] = (lk & 1) ? t1 : t0;
                t0 = __shfl_sync(0xffffffffu, p2, s2);
                t1 = __shfl_sync(0xffffffffu, p3, s2);
                ap[3] = (lk & 1) ? t1 : t0;

                #pragma unroll
                for (int ni = 0; ni < 8; ni++) {
                    unsigned b[2];
                    b[0] = __float_as_uint(Vp[kk * 8 + lk    ][ni * 8 + grp]);
                    b[1] = __float_as_uint(Vp[kk * 8 + lk + 4][ni * 8 + grp]);
                    mma_tf32(acc[ni], ap, b);
                }
            }
        }

        __syncthreads();   // all reads of buffer p done before it is refilled
        p ^= 1;
    }

    // ---- epilogue: normalize, write [b, s, h*64 + d] ----
    const float il0 = 1.0f / l_run[0];
    const float il1 = 1.0f / l_run[1];
    const int r0 = q0w + grp;
    const int r1 = r0 + 8;
    #pragma unroll
    for (int ni = 0; ni < 8; ni++) {
        int col = h * HD + ni * 8 + 2 * lk;
        float2 v0 = { acc[ni][0] * il0, acc[ni][1] * il0 };
        float2 v1 = { acc[ni][2] * il1, acc[ni][3] * il1 };
        *(float2*)&out[(size_t)(b_ * S_LEN + r0) * D_MODEL + col] = v0;
        *(float2*)&out[(size_t)(b_ * S_LEN + r1) * D_MODEL + col] = v1;
    }
}

// ---------------------------------------------------------------------------
extern "C" void kernel_launch(void* const* d_in, const int* in_sizes, int n_in,
                              void* d_out, int out_size)
{
    (void)in_sizes; (void)n_in; (void)out_size;
    const float* hs    = (const float*)d_in[0];
    const int*   amask = (const int*)  d_in[1];
    const float* Wq    = (const float*)d_in[2];
    const float* bq    = (const float*)d_in[3];
    const float* Wk    = (const float*)d_in[4];
    const float* bk    = (const float*)d_in[5];
    const float* Wv    = (const float*)d_in[6];
    const float* bv    = (const float*)d_in[7];
    float* out = (float*)d_out;

    // 0) pre-round X, W to tf32 bits
    const size_t n4 = ((size_t)M_TOTAL * D_MODEL + 3ull * D_MODEL * D_MODEL) / 4;
    cvt_prepass<<<(unsigned)((n4 + 255) / 256), 256>>>(hs, Wq, Wk, Wv);

    // 1) QKV projection
    const int proj_smem = 4 * GTILE * (int)sizeof(unsigned);   // 73728 B
    cudaFuncSetAttribute(qkv_gemm_tf32,
                         cudaFuncAttributeMaxDynamicSharedMemorySize, proj_smem);
    dim3 ggrid(D_MODEL / GBN, M_TOTAL / GBM, 3);               // (8, 64, 3)
    qkv_gemm_tf32<<<ggrid, 256, proj_smem>>>(bq, bk, bv);

    // 2) attention: 2 x (K 64x68 + V 64x72) words = 71680 B, 2 CTAs/SM (regs)
    const int attn_smem = 2 * KVTILE * (int)sizeof(unsigned);
    cudaFuncSetAttribute(attn_tc,
                         cudaFuncAttributeMaxDynamicSharedMemorySize, attn_smem);
    attn_tc<<<dim3(S_LEN / QT, BATCH * NH), 256, attn_smem>>>(amask, out);
}

// round 11
// speedup vs baseline: 1.4714x; 1.4714x over previous
#include <cuda_runtime.h>
#include <math.h>

#define S_LEN   2048
#define D_MODEL 1024
#define NH      16
#define HD      64
#define BATCH   4
#define M_TOTAL (BATCH * S_LEN)          // 8192
#define PLANE   (8192 * 1024)            // elems per Q/K/V plane

// Scratch (__device__ globals = sanctioned scratch, allocation-free rule):
//  g_qkv : Q,K,V in [b,h,s,d], values pre-rounded to tf32 (Q pre-scaled 0.125)
//  g_x32 : hidden_states pre-rounded to tf32 bits
//  g_w32 : Wq|Wk|Wv pre-rounded to tf32 bits
__device__ float    g_qkv[3ull * PLANE];
__device__ unsigned g_x32[(size_t)M_TOTAL * D_MODEL];
__device__ unsigned g_w32[3ull * D_MODEL * D_MODEL];

// ---------------------------------------------------------------------------
// tf32 mma helpers (m16n8k8, row.col, f32 accumulate)
//   A: a0=[grp][lk] a1=[grp+8][lk] a2=[grp][lk+4] a3=[grp+8][lk+4]
//   B (row-major [n][k]): b0=[n+grp][lk] b1=[n+grp][lk+4]
//   C: c0=[grp][2lk] c1=[grp][2lk+1] c2=[grp+8][2lk] c3=[grp+8][2lk+1]
// ---------------------------------------------------------------------------
__device__ __forceinline__ unsigned f2tf(float f) {
    unsigned u;
    asm("cvt.rna.tf32.f32 %0, %1;" : "=r"(u) : "f"(f));
    return u;
}

__device__ __forceinline__ void mma_tf32(float c[4], const unsigned a[4],
                                         const unsigned b[2]) {
    asm volatile(
        "mma.sync.aligned.m16n8k8.row.col.f32.tf32.tf32.f32 "
        "{%0,%1,%2,%3}, {%4,%5,%6,%7}, {%8,%9}, {%0,%1,%2,%3};"
        : "+f"(c[0]), "+f"(c[1]), "+f"(c[2]), "+f"(c[3])
        : "r"(a[0]), "r"(a[1]), "r"(a[2]), "r"(a[3]), "r"(b[0]), "r"(b[1]));
}

__device__ __forceinline__ void cp_async16(void* sp, const void* gp) {
    unsigned saddr = (unsigned)__cvta_generic_to_shared(sp);
    asm volatile("cp.async.cg.shared.global [%0], [%1], 16;\n"
                 :: "r"(saddr), "l"(gp));
}
#define CP_COMMIT() asm volatile("cp.async.commit_group;")
#define CP_WAIT(N)  asm volatile("cp.async.wait_group %0;" :: "n"(N))

// ---------------------------------------------------------------------------
// Kernel 0: pre-round X and W to tf32 bits (memory-bound, ~14us measured).
// ---------------------------------------------------------------------------
__global__ __launch_bounds__(256) void cvt_prepass(
    const float* __restrict__ X,
    const float* __restrict__ Wq, const float* __restrict__ Wk,
    const float* __restrict__ Wv)
{
    const size_t X4 = (size_t)M_TOTAL * D_MODEL / 4;
    const size_t W4 = (size_t)D_MODEL * D_MODEL / 4;
    size_t i = (size_t)blockIdx.x * blockDim.x + threadIdx.x;
    if (i >= X4 + 3 * W4) return;

    const float* src;
    unsigned*    dst;
    if (i < X4)                { src = X;  dst = g_x32;              }
    else if (i < X4 + W4)      { src = Wq; dst = g_w32;              i -= X4; }
    else if (i < X4 + 2 * W4)  { src = Wk; dst = g_w32 +     W4 * 4; i -= X4 + W4; }
    else                       { src = Wv; dst = g_w32 + 2 * W4 * 4; i -= X4 + 2 * W4; }

    float4 v = *(const float4*)(src + i * 4);
    uint4  u = { f2tf(v.x), f2tf(v.y), f2tf(v.z), f2tf(v.w) };
    *(uint4*)(dst + i * 4) = u;
}

// ---------------------------------------------------------------------------
// Kernel 1: fused QKV projection, tf32, cp.async double-buffered.
//   Inputs pre-rounded tf32 bits -> zero cvt in the mainloop. (R8-verified.)
// ---------------------------------------------------------------------------
#define GBM 128
#define GBN 128
#define GBK 32
#define GPAD (GBK + 4)               // 36 words
#define GTILE (GBM * GPAD)

__global__ __launch_bounds__(256, 2) void qkv_gemm_tf32(
    const float* __restrict__ bq, const float* __restrict__ bk,
    const float* __restrict__ bv)
{
    extern __shared__ unsigned psm[];   // As[2][128][36] | Bs[2][128][36]

    const int z = blockIdx.z;
    const unsigned* X    = g_x32;
    const unsigned* W    = g_w32 + (size_t)z * D_MODEL * D_MODEL;
    const float*    bias = (z == 0) ? bq : (z == 1) ? bk : bv;
    const float     scale = (z == 0) ? 0.125f : 1.0f;
    float* Out = g_qkv + (size_t)z * PLANE;

    const int tid    = threadIdx.x;
    const int warp   = tid >> 5;
    const int lane   = tid & 31;
    const int grp    = lane >> 2;
    const int lk     = lane & 3;
    const int warp_m = warp >> 2;
    const int warp_n = warp & 3;
    const int m0 = blockIdx.y * GBM;
    const int n0 = blockIdx.x * GBN;

    const int sr  = tid >> 3;
    const int sc4 = tid & 7;

    float acc[4][4][4];
    #pragma unroll
    for (int mi = 0; mi < 4; mi++)
        #pragma unroll
        for (int ni = 0; ni < 4; ni++)
            #pragma unroll
            for (int r = 0; r < 4; r++) acc[mi][ni][r] = 0.f;

    #pragma unroll
    for (int it = 0; it < 4; it++) {
        int r = sr + it * 32;
        cp_async16(&psm[r * GPAD + sc4 * 4],
                   X + (size_t)(m0 + r) * D_MODEL + sc4 * 4);
        cp_async16(&psm[2 * GTILE + r * GPAD + sc4 * 4],
                   W + (size_t)(n0 + r) * D_MODEL + sc4 * 4);
    }
    CP_COMMIT();

    int p = 0;
    for (int k0 = 0; k0 < D_MODEL; k0 += GBK) {
        if (k0 + GBK < D_MODEL) {
            int q = p ^ 1;
            #pragma unroll
            for (int it = 0; it < 4; it++) {
                int r = sr + it * 32;
                cp_async16(&psm[q * GTILE + r * GPAD + sc4 * 4],
                           X + (size_t)(m0 + r) * D_MODEL + k0 + GBK + sc4 * 4);
                cp_async16(&psm[(2 + q) * GTILE + r * GPAD + sc4 * 4],
                           W + (size_t)(n0 + r) * D_MODEL + k0 + GBK + sc4 * 4);
            }
            CP_COMMIT();
            CP_WAIT(1);
        } else {
            CP_WAIT(0);
        }
        __syncthreads();

        const unsigned* Asb = psm + p * GTILE;
        const unsigned* Bsb = psm + (2 + p) * GTILE;

        #pragma unroll
        for (int kk = 0; kk < GBK; kk += 8) {
            unsigned a[4][4];
            #pragma unroll
            for (int mi = 0; mi < 4; mi++) {
                int rb = warp_m * 64 + mi * 16 + grp;
                a[mi][0] = Asb[(rb    ) * GPAD + kk + lk    ];
                a[mi][1] = Asb[(rb + 8) * GPAD + kk + lk    ];
                a[mi][2] = Asb[(rb    ) * GPAD + kk + lk + 4];
                a[mi][3] = Asb[(rb + 8) * GPAD + kk + lk + 4];
            }
            unsigned b[4][2];
            #pragma unroll
            for (int ni = 0; ni < 4; ni++) {
                int nb = warp_n * 32 + ni * 8 + grp;
                b[ni][0] = Bsb[nb * GPAD + kk + lk    ];
                b[ni][1] = Bsb[nb * GPAD + kk + lk + 4];
            }
            #pragma unroll
            for (int mi = 0; mi < 4; mi++)
                #pragma unroll
                for (int ni = 0; ni < 4; ni++)
                    mma_tf32(acc[mi][ni], a[mi], b[ni]);
        }
        __syncthreads();
        p ^= 1;
    }

    // epilogue: bias, pre-scale, round to tf32, scatter into [b, h, s, d]
    #pragma unroll
    for (int mi = 0; mi < 4; mi++) {
        #pragma unroll
        for (int half = 0; half < 2; half++) {
            int m  = m0 + warp_m * 64 + mi * 16 + grp + half * 8;
            int b_ = m >> 11;
            int s_ = m & 2047;
            #pragma unroll
            for (int ni = 0; ni < 4; ni++) {
                int n = n0 + warp_n * 32 + ni * 8 + 2 * lk;
                int h = n >> 6;
                int d = n & 63;
                float2 v;
                v.x = __uint_as_float(f2tf((acc[mi][ni][half * 2 + 0] + bias[n    ]) * scale));
                v.y = __uint_as_float(f2tf((acc[mi][ni][half * 2 + 1] + bias[n + 1]) * scale));
                *(float2*)&Out[(((size_t)(b_ * NH + h) * S_LEN + s_) << 6) + d] = v;
            }
        }
    }
}

// ---------------------------------------------------------------------------
// Kernel 2: causal flash attention, tf32 tensor cores (R7 config: the
// measured-best 323us shape). 128 threads (4 warps), QT=64, 4 CTAs/SM.
// Single-buffered K/V, but K and V are SEPARATE cp.async commit groups:
// wait for K only, compute S + full softmax (V not needed), then wait V
// before PV -> V's load latency hides behind S-mma + softmax.
// K: [key][68] (banks 4*grp+lk), V: [key][72] (banks 8*lk+grp).
// ---------------------------------------------------------------------------
#define QT   64
#define KT   64
#define KPAD 68
#define VPAD 72

__global__ __launch_bounds__(128, 4) void attn_tc(
    const int* __restrict__ amask, float* __restrict__ out)
{
    extern __shared__ unsigned sm[];
    unsigned (*Qs)[KPAD] = (unsigned(*)[KPAD])(sm);                   // [64][68] tf32 bits
    float    (*Ks)[KPAD] = (float(*)[KPAD])(sm +     QT * KPAD);      // [64][68]
    float    (*Vs)[VPAD] = (float(*)[VPAD])(sm + 2 * QT * KPAD);      // [64][72]

    const int qt = (gridDim.x - 1) - blockIdx.x;    // heavy blocks first
    const int bh = blockIdx.y;
    const int b_ = bh >> 4;
    const int h  = bh & 15;
    const int q0 = qt * QT;

    const float* Qb = g_qkv + (size_t)bh * S_LEN * HD;
    const float* Kb = g_qkv + (size_t)PLANE + (size_t)bh * S_LEN * HD;
    const float* Vb = g_qkv + 2ull * PLANE + (size_t)bh * S_LEN * HD;

    const int tid  = threadIdx.x;
    const int warp = tid >> 5;
    const int lane = tid & 31;
    const int grp  = lane >> 2;
    const int lk   = lane & 3;
    const int q0w  = q0 + warp * 16;

    // ---- stage Q bits (already tf32 + scaled): pure copy ----
    #pragma unroll
    for (int it = 0; it < 8; it++) {
        int idx = tid + it * 128;          // 0..1023
        int r   = idx >> 4;                // q row 0..63
        int c   = idx & 15;                // 16B chunk
        uint4 u = *(const uint4*)(Qb + (size_t)(q0 + r) * HD + c * 4);
        *(uint4*)&Qs[r][c * 4] = u;
    }

    float m_run[2] = { -1e30f, -1e30f };
    float l_run[2] = { 0.f, 0.f };
    float acc[8][4];
    #pragma unroll
    for (int ni = 0; ni < 8; ni++)
        #pragma unroll
        for (int r = 0; r < 4; r++) acc[ni][r] = 0.f;

    const int qsrc = lane & ~3;
    const int s1   = qsrc | (lk >> 1);
    const int s2   = s1 + 2;
    const int rb   = warp * 16;

    for (int j0 = 0; j0 <= q0; j0 += KT) {
        __syncthreads();                   // retire previous tile reads (+ Q STS on iter 0)

        // ---- stage K (group 1) and V (group 0) via cp.async ----
        #pragma unroll
        for (int it = 0; it < 8; it++) {
            int idx = tid + it * 128;      // 0..1023
            int r   = idx >> 4;            // key 0..63
            int c   = idx & 15;
            cp_async16(&Ks[r][c * 4], Kb + (size_t)(j0 + r) * HD + c * 4);
        }
        CP_COMMIT();                       // group: K
        #pragma unroll
        for (int it = 0; it < 8; it++) {
            int idx = tid + it * 128;
            int r   = idx >> 4;
            int c   = idx & 15;
            cp_async16(&Vs[r][c * 4], Vb + (size_t)(j0 + r) * HD + c * 4);
        }
        CP_COMMIT();                       // group: V
        CP_WAIT(1);                        // K ready (V may still be in flight)
        __syncthreads();

        // ---- S = Q K^T ----
        float s[8][4];
        #pragma unroll
        for (int ni = 0; ni < 8; ni++)
            #pragma unroll
            for (int r = 0; r < 4; r++) s[ni][r] = 0.f;

        #pragma unroll
        for (int kk = 0; kk < 8; kk++) {
            unsigned a[4];
            a[0] = Qs[rb + grp    ][kk * 8 + lk    ];
            a[1] = Qs[rb + grp + 8][kk * 8 + lk    ];
            a[2] = Qs[rb + grp    ][kk * 8 + lk + 4];
            a[3] = Qs[rb + grp + 8][kk * 8 + lk + 4];
            #pragma unroll
            for (int ni = 0; ni < 8; ni++) {
                unsigned b[2];
                b[0] = __float_as_uint(Ks[ni * 8 + grp][kk * 8 + lk    ]);
                b[1] = __float_as_uint(Ks[ni * 8 + grp][kk * 8 + lk + 4]);
                mma_tf32(s[ni], a, b);
            }
        }

        // ---- causal mask (tiles touching the diagonal) ----
        if (j0 + KT - 1 > q0w) {
            int r0 = q0w + grp;
            #pragma unroll
            for (int ni = 0; ni < 8; ni++) {
                int c0 = j0 + ni * 8 + 2 * lk;
                if (c0     > r0    ) s[ni][0] = -1e30f;
                if (c0 + 1 > r0    ) s[ni][1] = -1e30f;
                if (c0     > r0 + 8) s[ni][2] = -1e30f;
                if (c0 + 1 > r0 + 8) s[ni][3] = -1e30f;
            }
        }
        // ---- attention keep-mask ----
        #pragma unroll
        for (int ni = 0; ni < 8; ni++) {
            int2 km = *(const int2*)(amask + b_ * S_LEN + j0 + ni * 8 + 2 * lk);
            if (km.x == 0) { s[ni][0] = -1e30f; s[ni][2] = -1e30f; }
            if (km.y == 0) { s[ni][1] = -1e30f; s[ni][3] = -1e30f; }
        }

        // ---- online softmax (V load still overlapping) ----
        float mt0 = -1e30f, mt1 = -1e30f;
        #pragma unroll
        for (int ni = 0; ni < 8; ni++) {
            mt0 = fmaxf(mt0, fmaxf(s[ni][0], s[ni][1]));
            mt1 = fmaxf(mt1, fmaxf(s[ni][2], s[ni][3]));
        }
        mt0 = fmaxf(mt0, __shfl_xor_sync(0xffffffffu, mt0, 1, 4));
        mt0 = fmaxf(mt0, __shfl_xor_sync(0xffffffffu, mt0, 2, 4));
        mt1 = fmaxf(mt1, __shfl_xor_sync(0xffffffffu, mt1, 1, 4));
        mt1 = fmaxf(mt1, __shfl_xor_sync(0xffffffffu, mt1, 2, 4));

        float mn0 = fmaxf(m_run[0], mt0);
        float mn1 = fmaxf(m_run[1], mt1);
        float al0 = __expf(m_run[0] - mn0);
        float al1 = __expf(m_run[1] - mn1);
        m_run[0] = mn0; m_run[1] = mn1;

        float lt0 = 0.f, lt1 = 0.f;
        #pragma unroll
        for (int ni = 0; ni < 8; ni++) {
            s[ni][0] = __expf(s[ni][0] - mn0); lt0 += s[ni][0];
            s[ni][1] = __expf(s[ni][1] - mn0); lt0 += s[ni][1];
            s[ni][2] = __expf(s[ni][2] - mn1); lt1 += s[ni][2];
            s[ni][3] = __expf(s[ni][3] - mn1); lt1 += s[ni][3];
        }
        lt0 += __shfl_xor_sync(0xffffffffu, lt0, 1, 4);
        lt0 += __shfl_xor_sync(0xffffffffu, lt0, 2, 4);
        lt1 += __shfl_xor_sync(0xffffffffu, lt1, 1, 4);
        lt1 += __shfl_xor_sync(0xffffffffu, lt1, 2, 4);
        l_run[0] = l_run[0] * al0 + lt0;
        l_run[1] = l_run[1] * al1 + lt1;

        #pragma unroll
        for (int ni = 0; ni < 8; ni++) {
            acc[ni][0] *= al0; acc[ni][1] *= al0;
            acc[ni][2] *= al1; acc[ni][3] *= al1;
        }

        CP_WAIT(0);                        // V ready
        __syncthreads();

        // ---- P (C-frag) -> A-frag via quad shuffles, acc += P V ----
        #pragma unroll
        for (int kk = 0; kk < 8; kk++) {
            unsigned p0 = f2tf(s[kk][0]), p1 = f2tf(s[kk][1]);
            unsigned p2 = f2tf(s[kk][2]), p3 = f2tf(s[kk][3]);
            unsigned ap[4], t0, t1;
            t0 = __shfl_sync(0xffffffffu, p0, s1);
            t1 = __shfl_sync(0xffffffffu, p1, s1);
            ap[0] = (lk & 1) ? t1 : t0;
            t0 = __shfl_sync(0xffffffffu, p2, s1);
            t1 = __shfl_sync(0xffffffffu, p3, s1);
            ap[1] = (lk & 1) ? t1 : t0;
            t0 = __shfl_sync(0xffffffffu, p0, s2);
            t1 = __shfl_sync(0xffffffffu, p1, s2);
            ap[2] = (lk & 1) ? t1 : t0;
            t0 = __shfl_sync(0xffffffffu, p2, s2);
            t1 = __shfl_sync(0xffffffffu, p3, s2);
            ap[3] = (lk & 1) ? t1 : t0;

            #pragma unroll
            for (int ni = 0; ni < 8; ni++) {
                unsigned b[2];
                b[0] = __float_as_uint(Vs[kk * 8 + lk    ][ni * 8 + grp]);
                b[1] = __float_as_uint(Vs[kk * 8 + lk + 4][ni * 8 + grp]);
                mma_tf32(acc[ni], ap, b);
            }
        }
    }

    // ---- epilogue: normalize, write [b, s, h*64 + d] ----
    const float il0 = 1.0f / l_run[0];
    const float il1 = 1.0f / l_run[1];
    const int r0 = q0w + grp;
    const int r1 = r0 + 8;
    #pragma unroll
    for (int ni = 0; ni < 8; ni++) {
        int col = h * HD + ni * 8 + 2 * lk;
        float2 v0 = { acc[ni][0] * il0, acc[ni][1] * il0 };
        float2 v1 = { acc[ni][2] * il1, acc[ni][3] * il1 };
        *(float2*)&out[(size_t)(b_ * S_LEN + r0) * D_MODEL + col] = v0;
        *(float2*)&out[(size_t)(b_ * S_LEN + r1) * D_MODEL + col] = v1;
    }
}

// ---------------------------------------------------------------------------
extern "C" void kernel_launch(void* const* d_in, const int* in_sizes, int n_in,
                              void* d_out, int out_size)
{
    (void)in_sizes; (void)n_in; (void)out_size;
    const float* hs    = (const float*)d_in[0];
    const int*   amask = (const int*)  d_in[1];
    const float* Wq    = (const float*)d_in[2];
    const float* bq    = (const float*)d_in[3];
    const float* Wk    = (const float*)d_in[4];
    const float* bk    = (const float*)d_in[5];
    const float* Wv    = (const float*)d_in[6];
    const float* bv    = (const float*)d_in[7];
    float* out = (float*)d_out;

    // 0) pre-round X, W to tf32 bits
    const size_t n4 = ((size_t)M_TOTAL * D_MODEL + 3ull * D_MODEL * D_MODEL) / 4;
    cvt_prepass<<<(unsigned)((n4 + 255) / 256), 256>>>(hs, Wq, Wk, Wv);

    // 1) QKV projection
    const int proj_smem = 4 * GTILE * (int)sizeof(unsigned);   // 73728 B
    cudaFuncSetAttribute(qkv_gemm_tf32,
                         cudaFuncAttributeMaxDynamicSharedMemorySize, proj_smem);
    dim3 ggrid(D_MODEL / GBN, M_TOTAL / GBM, 3);               // (8, 64, 3)
    qkv_gemm_tf32<<<ggrid, 256, proj_smem>>>(bq, bk, bv);

    // 2) attention: Qs 64*68 + Ks 64*68 + Vs 64*72 = 53248 B (4 CTAs/SM)
    const int attn_smem = (QT * KPAD + KT * KPAD + KT * VPAD) * (int)sizeof(unsigned);
    cudaFuncSetAttribute(attn_tc,
                         cudaFuncAttributeMaxDynamicSharedMemorySize, attn_smem);
    attn_tc<<<dim3(S_LEN / QT, BATCH * NH), 128, attn_smem>>>(amask, out);
}